// round 16
// baseline (speedup 1.0000x reference)
#include <cuda_runtime.h>
#include <cuda_bf16.h>
#include <math.h>
#include <stdint.h>

#define BB   32
#define SS   512
#define INF  512
#define HH   1024
#define NG   4096
#define NCTA 128

__device__ float g_gxT[(size_t)SS * NG * BB];   // x-part gates, [s][n][b]
__device__ unsigned g_barCnt;
__device__ unsigned g_barRel;

// K-concat hi/lo bf16 buffers. A row: [hi | lo | hi], B row: [hi | hi | lo].
// g_Abig doubles as recurrent h buffer: row = b*512 + t, stride 3072.
__device__ __nv_bfloat16 g_Abig[(size_t)16384 * 3072];
__device__ __nv_bfloat16 g_B0big[(size_t)4096 * 1536];
__device__ __nv_bfloat16 g_B1big[(size_t)4096 * 3072];

// ---------------------------------------------------------------------------
__global__ void split_x(const float* __restrict__ x) {
    int idx = blockIdx.x * blockDim.x + threadIdx.x;
    if (idx == 0) { g_barCnt = 0u; g_barRel = 0u; }
    if (idx >= 16384 * 512) return;
    int r = idx >> 9, c = idx & 511;
    float v = x[idx];
    __nv_bfloat16 h = __float2bfloat16(v);
    __nv_bfloat16 l = __float2bfloat16(v - __bfloat162float(h));
    size_t base = (size_t)r * 3072;
    g_Abig[base + c]        = h;
    g_Abig[base + 512 + c]  = l;
    g_Abig[base + 1024 + c] = h;
}

__global__ void split_w(const float* __restrict__ W, int ldw, int cols,
                        __nv_bfloat16* __restrict__ dst, int ldd)
{
    int idx = blockIdx.x * blockDim.x + threadIdx.x;
    if (idx >= 4096 * cols) return;
    int r = idx / cols, c = idx - r * cols;
    float v = W[(size_t)r * ldw + c];
    __nv_bfloat16 h = __float2bfloat16(v);
    __nv_bfloat16 l = __float2bfloat16(v - __bfloat162float(h));
    size_t base = (size_t)r * ldd;
    dst[base + c]            = h;
    dst[base + cols + c]     = h;
    dst[base + 2 * cols + c] = l;
}

// ---------------------------------------------------------------------------
__device__ __forceinline__ void mma16816(float* d, const uint32_t* a,
                                         const uint32_t* b)
{
    asm volatile(
        "mma.sync.aligned.m16n8k16.row.col.f32.bf16.bf16.f32 "
        "{%0,%1,%2,%3}, {%4,%5,%6,%7}, {%8,%9}, {%0,%1,%2,%3};\n"
        : "+f"(d[0]), "+f"(d[1]), "+f"(d[2]), "+f"(d[3])
        : "r"(a[0]), "r"(a[1]), "r"(a[2]), "r"(a[3]), "r"(b[0]), "r"(b[1]));
}

__device__ __forceinline__ void ldsm4(uint32_t* r, uint32_t addr) {
    asm volatile(
        "ldmatrix.sync.aligned.m8n8.x4.shared.b16 {%0,%1,%2,%3}, [%4];"
        : "=r"(r[0]), "=r"(r[1]), "=r"(r[2]), "=r"(r[3]) : "r"(addr));
}

__device__ __forceinline__ uint32_t smaddr(const void* p) {
    return (uint32_t)__cvta_generic_to_shared(p);
}
#define CP16(dst, src) \
    asm volatile("cp.async.cg.shared.global [%0], [%1], 16;" :: "r"(dst), "l"(src))
#define CPCOMMIT() asm volatile("cp.async.commit_group;")
template<int N> __device__ __forceinline__ void cpwaitc() {
    asm volatile("cp.async.wait_group %0;" :: "n"(N));
}

__device__ __forceinline__ void mbar_wait(uint32_t mbar, uint32_t parity) {
    uint32_t done;
    asm volatile(
        "{\n\t.reg .pred p;\n\t"
        "mbarrier.try_wait.parity.acquire.cta.shared::cta.b64 p, [%1], %2;\n\t"
        "selp.b32 %0, 1, 0, p;\n\t}"
        : "=r"(done) : "r"(mbar), "r"(parity) : "memory");
    if (!done) {
        asm volatile(
            "{\n\t.reg .pred P1;\n\t"
            "WL_%=:\n\t"
            "mbarrier.try_wait.parity.acquire.cta.shared::cta.b64 P1, [%0], %1, 0x989680;\n\t"
            "@P1 bra.uni WD_%=;\n\t"
            "bra.uni WL_%=;\n\t"
            "WD_%=:\n\t}"
            :: "r"(mbar), "r"(parity) : "memory");
    }
}

#define BULKCP(dst, src, bytes, mbar) \
    asm volatile( \
        "cp.async.bulk.shared::cluster.global.mbarrier::complete_tx::bytes " \
        "[%0], [%1], %2, [%3];" \
        :: "r"(dst), "l"(src), "r"(bytes), "r"(mbar) : "memory")

// ---------------------------------------------------------------------------
// bf16 GEMM (x-projection): proven R11 version — ldmatrix frags + 3-stage
// cp.async pipeline (tail-fixed). CTA 128x64, 8 warps (32x32), 2 CTAs/SM.
#define STW        (192 * 36)
#define GX_SMEM_BYTES (3 * STW * 4)

__global__ __launch_bounds__(256, 2) void gemm_x_bf16(
    const __nv_bfloat16* __restrict__ A, int lda,
    const __nv_bfloat16* __restrict__ B, int ldb,
    const float* __restrict__ bias, int K)
{
    extern __shared__ uint32_t smg[];

    const int tid  = threadIdx.x;
    const int n0   = blockIdx.x * 64;
    const int m0   = blockIdx.y * 128;
    const int wid  = tid >> 5, lane = tid & 31;
    const int wm   = (wid >> 1) * 32;
    const int wn   = (wid & 1) * 32;
    const int g    = lane >> 2, t = lane & 3;

    const uint32_t smb = smaddr(smg);

    const int aoffw = (wm + (lane & 15)) * 36 + (lane >> 4) * 4;
    const int boffw = 128 * 36
                    + (wn + ((lane >> 4) & 1) * 8 + (lane & 7)) * 36
                    + ((lane >> 3) & 1) * 4;

    float acc[2][4][4];
#pragma unroll
    for (int mt = 0; mt < 2; mt++)
#pragma unroll
        for (int nt = 0; nt < 4; nt++)
#pragma unroll
            for (int i = 0; i < 4; i++) acc[mt][nt][i] = 0.0f;

    const int nch = K / 64;

    auto stage = [&](int st, int k0) {
        uint32_t base = smb + st * (STW * 4);
#pragma unroll
        for (int i = 0; i < 4; i++) {
            int q = i * 256 + tid;
            int r = q >> 3, c = q & 7;
            CP16(base + (r * 36 + c * 4) * 4,
                 A + (size_t)(m0 + r) * lda + k0 + c * 8);
        }
#pragma unroll
        for (int i = 0; i < 2; i++) {
            int q = i * 256 + tid;
            int r = q >> 3, c = q & 7;
            CP16(base + (128 * 36 + r * 36 + c * 4) * 4,
                 B + (size_t)(n0 + r) * ldb + k0 + c * 8);
        }
        CPCOMMIT();
    };

    stage(0, 0);
    stage(1, 64);

    for (int ch = 0; ch < nch; ch++) {
        if (ch + 1 < nch) cpwaitc<1>(); else cpwaitc<0>();
        __syncthreads();
        if (ch + 2 < nch) stage((ch + 2) % 3, (ch + 2) * 64);

        const uint32_t sA = smb + (ch % 3) * (STW * 4) + aoffw * 4;
        const uint32_t sB = smb + (ch % 3) * (STW * 4) + boffw * 4;

#pragma unroll
        for (int kk = 0; kk < 4; kk++) {
            uint32_t a0[4], a1[4], b0[4], b1[4];
            ldsm4(a0, sA + kk * 32);
            ldsm4(a1, sA + 16 * 36 * 4 + kk * 32);
            ldsm4(b0, sB + kk * 32);
            ldsm4(b1, sB + 16 * 36 * 4 + kk * 32);
            mma16816(acc[0][0], a0, b0);
            mma16816(acc[1][0], a1, b0);
            mma16816(acc[0][1], a0, b0 + 2);
            mma16816(acc[1][1], a1, b0 + 2);
            mma16816(acc[0][2], a0, b1);
            mma16816(acc[1][2], a1, b1);
            mma16816(acc[0][3], a0, b1 + 2);
            mma16816(acc[1][3], a1, b1 + 2);
        }
    }

#pragma unroll
    for (int mt = 0; mt < 2; mt++) {
        int m1 = m0 + wm + mt * 16 + g;
        int m2 = m1 + 8;
        int b1 = m1 >> 9, s1 = m1 & 511;
        int b2 = m2 >> 9, s2 = m2 & 511;
#pragma unroll
        for (int nt = 0; nt < 4; nt++) {
            int n = n0 + wn + nt * 8 + 2 * t;
            float2 bv = *(const float2*)&bias[n];
            size_t o1 = ((size_t)s1 * NG + n) * BB + b1;
            size_t o2 = ((size_t)s2 * NG + n) * BB + b2;
            g_gxT[o1]      = acc[mt][nt][0] + bv.x;
            g_gxT[o1 + BB] = acc[mt][nt][1] + bv.y;
            g_gxT[o2]      = acc[mt][nt][2] + bv.x;
            g_gxT[o2 + BB] = acc[mt][nt][3] + bv.y;
        }
    }
}

// ---------------------------------------------------------------------------
// Persistent recurrent kernel v4: h staged via TWO half bulk copies (rows
// 0-15 -> mbar0, rows 16-31 -> mbar1); mma restructured mt-outer so the
// second half-copy overlaps the first half's mma. W-lo in registers.
#define LHOFFW  16512
#define LROWW   1028
#define LPARTW  49408
#define LMBARW  57856          // mbar0 @ +0, mbar1 @ +2 words (8B each)
#define LS_SMEM_BYTES 231488

__global__ __launch_bounds__(256, 1) void lstm_layer(
    const float* __restrict__ W, int ldw, int Din,
    float* __restrict__ out, int layer, int rbase)
{
    extern __shared__ uint32_t smu[];
    uint32_t* Wsh  = smu;
    uint32_t* WslT = smu + LHOFFW;           // temp W-lo (inside h region)
    float*    part = (float*)(smu + LPARTW);
    const uint32_t smb   = smaddr(smu);
    const uint32_t mbar0 = smb + LMBARW * 4;
    const uint32_t mbar1 = mbar0 + 8;

    const int tid  = threadIdx.x;
    const int j0   = blockIdx.x * 8;
    const int wid  = tid >> 5, lane = tid & 31;
    const int g    = lane >> 2, t4 = lane & 3;

    // ---- Load + split recurrent W slice once (32 rows x 1024 k) ----
    for (int i = 0; i < 64; i++) {
        int q  = i * 256 + tid;
        int l  = q >> 9;
        int wk = q & 511;
        int gate = l >> 3, jj = l & 7;
        int n = gate * 1024 + j0 + jj;
        float2 v = *(const float2*)(W + (size_t)n * ldw + Din + wk * 2);
        __nv_bfloat16 hx = __float2bfloat16(v.x);
        __nv_bfloat16 hy = __float2bfloat16(v.y);
        __nv_bfloat16 lx = __float2bfloat16(v.x - __bfloat162float(hx));
        __nv_bfloat16 ly = __float2bfloat16(v.y - __bfloat162float(hy));
        Wsh[l * 516 + wk]  = (uint32_t)__bfloat16_as_ushort(hx)
                           | ((uint32_t)__bfloat16_as_ushort(hy) << 16);
        WslT[l * 516 + wk] = (uint32_t)__bfloat16_as_ushort(lx)
                           | ((uint32_t)__bfloat16_as_ushort(ly) << 16);
    }
    if (tid == 0) {
        asm volatile("mbarrier.init.shared.b64 [%0], %1;"
                     :: "r"(mbar0), "r"(1u) : "memory");
        asm volatile("mbarrier.init.shared.b64 [%0], %1;"
                     :: "r"(mbar1), "r"(1u) : "memory");
    }
    __syncthreads();

    // ---- Preload W-lo fragments into registers (loop-invariant) ----
    uint32_t wl[8][4][2];
#pragma unroll
    for (int sc = 0; sc < 8; sc++) {
        int bw = (sc * 8 + wid) * 8 + t4;
#pragma unroll
        for (int nt = 0; nt < 4; nt++) {
            int rn = nt * 8 + g;
            wl[sc][nt][0] = WslT[rn * 516 + bw];
            wl[sc][nt][1] = WslT[rn * 516 + bw + 4];
        }
    }
    __syncthreads();

    const int uj = tid & 7;
    const int ub = tid >> 3;
    const int ujglob = j0 + uj;

    float c_state = 0.0f;
    float h_last  = 0.0f;

    for (int tstep = 0; tstep < SS; tstep++) {
        size_t gbase = ((size_t)tstep * NG + ujglob) * BB + ub;
        float pi = g_gxT[gbase];
        float pf = g_gxT[gbase + (size_t)1024 * BB];
        float pg = g_gxT[gbase + (size_t)2048 * BB];
        float po = g_gxT[gbase + (size_t)3072 * BB];

        // ---- grid barrier (proven single-counter) ----
        unsigned round = (unsigned)(rbase + tstep + 1);
        __threadfence();
        __syncthreads();
        if (tid == 0) {
            unsigned arrived = atomicAdd(&g_barCnt, 1u) + 1u;
            if (arrived == round * NCTA) {
                atomicExch(&g_barRel, round);
            } else {
                volatile unsigned* rel = &g_barRel;
                while (*rel < round) {}
            }
            __threadfence();
        }
        __syncthreads();

        if (tstep > 0) {
            // ---- two half bulk copies: rows 0-15 -> mbar0, 16-31 -> mbar1
            if (wid == 0) {
                if (lane == 0) {
                    asm volatile(
                        "mbarrier.arrive.expect_tx.shared.b64 _, [%0], %1;"
                        :: "r"(mbar0), "r"(65536u) : "memory");
                } else if (lane == 1) {
                    asm volatile(
                        "mbarrier.arrive.expect_tx.shared.b64 _, [%0], %1;"
                        :: "r"(mbar1), "r"(65536u) : "memory");
                }
                __syncwarp();
                uint32_t dstb = smb + (LHOFFW + lane * LROWW) * 4;
                const __nv_bfloat16* srcp =
                    g_Abig + (size_t)(lane * 512 + tstep - 1) * 3072;
                BULKCP(dstb, srcp, 4096u, (lane < 16) ? mbar0 : mbar1);
            }

            float acc[2][4][4];
#pragma unroll
            for (int mt = 0; mt < 2; mt++)
#pragma unroll
                for (int nt = 0; nt < 4; nt++)
#pragma unroll
                    for (int i = 0; i < 4; i++) acc[mt][nt][i] = 0.0f;

            unsigned par = (unsigned)((tstep - 1) & 1);

            // ---- phase A: rows 0-15 (mt = 0), overlaps second half-copy
            mbar_wait(mbar0, par);
#pragma unroll
            for (int sc = 0; sc < 8; sc++) {
                const int kw = (sc * 8 + wid) * 8 + t4;
                uint32_t ah[4], al[4];
                {
                    int rb = LHOFFW + g * LROWW + kw;
                    ah[0] = smu[rb];
                    ah[1] = smu[rb + 8 * LROWW];
                    ah[2] = smu[rb + 4];
                    ah[3] = smu[rb + 8 * LROWW + 4];
                    al[0] = smu[rb + 512];
                    al[1] = smu[rb + 8 * LROWW + 512];
                    al[2] = smu[rb + 516];
                    al[3] = smu[rb + 8 * LROWW + 516];
                }
#pragma unroll
                for (int nt = 0; nt < 4; nt++) {
                    int rn = nt * 8 + g;
                    uint32_t bh[2];
                    bh[0] = Wsh[rn * 516 + kw];
                    bh[1] = Wsh[rn * 516 + kw + 4];
                    mma16816(acc[0][nt], ah, bh);
                    mma16816(acc[0][nt], ah, wl[sc][nt]);
                    mma16816(acc[0][nt], al, bh);
                }
            }

            // ---- phase B: rows 16-31 (mt = 1)
            mbar_wait(mbar1, par);
#pragma unroll
            for (int sc = 0; sc < 8; sc++) {
                const int kw = (sc * 8 + wid) * 8 + t4;
                uint32_t ah[4], al[4];
                {
                    int rb = LHOFFW + (16 + g) * LROWW + kw;
                    ah[0] = smu[rb];
                    ah[1] = smu[rb + 8 * LROWW];
                    ah[2] = smu[rb + 4];
                    ah[3] = smu[rb + 8 * LROWW + 4];
                    al[0] = smu[rb + 512];
                    al[1] = smu[rb + 8 * LROWW + 512];
                    al[2] = smu[rb + 516];
                    al[3] = smu[rb + 8 * LROWW + 516];
                }
#pragma unroll
                for (int nt = 0; nt < 4; nt++) {
                    int rn = nt * 8 + g;
                    uint32_t bh[2];
                    bh[0] = Wsh[rn * 516 + kw];
                    bh[1] = Wsh[rn * 516 + kw + 4];
                    mma16816(acc[1][nt], ah, bh);
                    mma16816(acc[1][nt], ah, wl[sc][nt]);
                    mma16816(acc[1][nt], al, bh);
                }
            }

            // partials -> smem (scalar: stride 33 is odd)
#pragma unroll
            for (int mt = 0; mt < 2; mt++) {
                int b = mt * 16 + g;
#pragma unroll
                for (int nt = 0; nt < 4; nt++) {
                    int l = nt * 8 + 2 * t4;
                    part[(wid * 32 + b) * 33 + l]     = acc[mt][nt][0];
                    part[(wid * 32 + b) * 33 + l + 1] = acc[mt][nt][1];
                    part[(wid * 32 + b + 8) * 33 + l]     = acc[mt][nt][2];
                    part[(wid * 32 + b + 8) * 33 + l + 1] = acc[mt][nt][3];
                }
            }
            __syncthreads();

#pragma unroll
            for (int w = 0; w < 8; w++) {
                int base = (w * 32 + ub) * 33 + uj;
                pi += part[base];
                pf += part[base + 8];
                pg += part[base + 16];
                po += part[base + 24];
            }
        }

        float gi = 1.0f / (1.0f + expf(-pi));
        float gf = 1.0f / (1.0f + expf(-pf));
        float gg = tanhf(pg);
        float go = 1.0f / (1.0f + expf(-po));
        c_state = gf * c_state + gi * gg;
        float h = go * tanhf(c_state);
        h_last = h;
        __nv_bfloat16 hh = __float2bfloat16(h);
        __nv_bfloat16 hl = __float2bfloat16(h - __bfloat162float(hh));
        size_t row = (size_t)(ub * 512 + tstep) * 3072;
        g_Abig[row + ujglob]        = hh;
        g_Abig[row + 1024 + ujglob] = hl;
        g_Abig[row + 2048 + ujglob] = hh;
    }

    out[32768 + layer * 32768 + ub * 1024 + ujglob] = h_last;
    out[98304 + layer * 32768 + ub * 1024 + ujglob] = c_state;
    if (layer == 1) out[ub * 1024 + ujglob] = h_last;
}

// ---------------------------------------------------------------------------
extern "C" void kernel_launch(void* const* d_in, const int* in_sizes, int n_in,
                              void* d_out, int out_size)
{
    const float* x  = (const float*)d_in[0];
    const float* W0 = (const float*)d_in[1];
    const float* b0 = (const float*)d_in[2];
    const float* W1 = (const float*)d_in[3];
    const float* b1 = (const float*)d_in[4];
    float* out = (float*)d_out;

    cudaFuncSetAttribute(lstm_layer,
        cudaFuncAttributeMaxDynamicSharedMemorySize, LS_SMEM_BYTES);
    cudaFuncSetAttribute(gemm_x_bf16,
        cudaFuncAttributeMaxDynamicSharedMemorySize, GX_SMEM_BYTES);

    __nv_bfloat16 *Abig, *B0big, *B1big;
    cudaGetSymbolAddress((void**)&Abig,  g_Abig);
    cudaGetSymbolAddress((void**)&B0big, g_B0big);
    cudaGetSymbolAddress((void**)&B1big, g_B1big);

    split_x<<<(16384 * 512 + 255) / 256, 256>>>(x);                       // 0
    split_w<<<(4096 * 512 + 255) / 256, 256>>>(W0, INF + HH, 512, B0big, 1536); // 1
    gemm_x_bf16<<<dim3(64, 128), 256, GX_SMEM_BYTES>>>(
        Abig, 3072, B0big, 1536, b0, 1536);                               // 2
    lstm_layer<<<NCTA, 256, LS_SMEM_BYTES>>>(W0, INF + HH, INF, out, 0, 0); // 3
    split_w<<<(4096 * 1024 + 255) / 256, 256>>>(W1, HH + HH, 1024, B1big, 3072); // 4
    gemm_x_bf16<<<dim3(64, 128), 256, GX_SMEM_BYTES>>>(
        Abig, 3072, B1big, 3072, b1, 3072);                               // 5
    lstm_layer<<<NCTA, 256, LS_SMEM_BYTES>>>(W1, HH + HH, HH, out, 1, 512); // 6
}

// round 17
// speedup vs baseline: 1.0623x; 1.0623x over previous
#include <cuda_runtime.h>
#include <cuda_bf16.h>
#include <math.h>
#include <stdint.h>

#define BB   32
#define SS   512
#define INF  512
#define HH   1024
#define NG   4096
#define NCTA 128

__device__ float g_gxT[(size_t)SS * NG * BB];   // x-part gates, [s][n][b]
__device__ unsigned g_barCnt;
__device__ unsigned g_barRel;

// Split layout v2: A rows [hi(0:D) | lo(D:2D)], stride 2048.
// g_Abig doubles as recurrent h buffer: row = b*512 + t (hi at col j, lo at
// 1024+j), so one 4KB bulk copy grabs hi+lo for a batch row.
__device__ __nv_bfloat16 g_Abig[(size_t)16384 * 3072];
__device__ __nv_bfloat16 g_B0big[(size_t)4096 * 1536];
__device__ __nv_bfloat16 g_B1big[(size_t)4096 * 3072];

// ---------------------------------------------------------------------------
__global__ void split_x(const float* __restrict__ x) {
    int idx = blockIdx.x * blockDim.x + threadIdx.x;
    if (idx == 0) { g_barCnt = 0u; g_barRel = 0u; }
    if (idx >= 16384 * 512) return;
    int r = idx >> 9, c = idx & 511;
    float v = x[idx];
    __nv_bfloat16 h = __float2bfloat16(v);
    __nv_bfloat16 l = __float2bfloat16(v - __bfloat162float(h));
    size_t base = (size_t)r * 2048;
    g_Abig[base + c]       = h;
    g_Abig[base + 512 + c] = l;
}

__global__ void split_w(const float* __restrict__ W, int ldw, int cols,
                        __nv_bfloat16* __restrict__ dst, int ldd)
{
    int idx = blockIdx.x * blockDim.x + threadIdx.x;
    if (idx >= 4096 * cols) return;
    int r = idx / cols, c = idx - r * cols;
    float v = W[(size_t)r * ldw + c];
    __nv_bfloat16 h = __float2bfloat16(v);
    __nv_bfloat16 l = __float2bfloat16(v - __bfloat162float(h));
    size_t base = (size_t)r * ldd;
    dst[base + c]        = h;
    dst[base + cols + c] = l;
}

// ---------------------------------------------------------------------------
__device__ __forceinline__ void mma16816(float* d, const uint32_t* a,
                                         const uint32_t* b)
{
    asm volatile(
        "mma.sync.aligned.m16n8k16.row.col.f32.bf16.bf16.f32 "
        "{%0,%1,%2,%3}, {%4,%5,%6,%7}, {%8,%9}, {%0,%1,%2,%3};\n"
        : "+f"(d[0]), "+f"(d[1]), "+f"(d[2]), "+f"(d[3])
        : "r"(a[0]), "r"(a[1]), "r"(a[2]), "r"(a[3]), "r"(b[0]), "r"(b[1]));
}

__device__ __forceinline__ void ldsm4(uint32_t* r, uint32_t addr) {
    asm volatile(
        "ldmatrix.sync.aligned.m8n8.x4.shared.b16 {%0,%1,%2,%3}, [%4];"
        : "=r"(r[0]), "=r"(r[1]), "=r"(r[2]), "=r"(r[3]) : "r"(addr));
}

__device__ __forceinline__ uint32_t smaddr(const void* p) {
    return (uint32_t)__cvta_generic_to_shared(p);
}
#define CP16(dst, src) \
    asm volatile("cp.async.cg.shared.global [%0], [%1], 16;" :: "r"(dst), "l"(src))
#define CPCOMMIT() asm volatile("cp.async.commit_group;")
template<int N> __device__ __forceinline__ void cpwaitc() {
    asm volatile("cp.async.wait_group %0;" :: "n"(N));
}

__device__ __forceinline__ void mbar_wait(uint32_t mbar, uint32_t parity) {
    uint32_t done;
    asm volatile(
        "{\n\t.reg .pred p;\n\t"
        "mbarrier.try_wait.parity.acquire.cta.shared::cta.b64 p, [%1], %2;\n\t"
        "selp.b32 %0, 1, 0, p;\n\t}"
        : "=r"(done) : "r"(mbar), "r"(parity) : "memory");
    if (!done) {
        asm volatile(
            "{\n\t.reg .pred P1;\n\t"
            "WL_%=:\n\t"
            "mbarrier.try_wait.parity.acquire.cta.shared::cta.b64 P1, [%0], %1, 0x989680;\n\t"
            "@P1 bra.uni WD_%=;\n\t"
            "bra.uni WL_%=;\n\t"
            "WD_%=:\n\t}"
            :: "r"(mbar), "r"(parity) : "memory");
    }
}

#define BULKCP(dst, src, bytes, mbar) \
    asm volatile( \
        "cp.async.bulk.shared::cluster.global.mbarrier::complete_tx::bytes " \
        "[%0], [%1], %2, [%3];" \
        :: "r"(dst), "l"(src), "r"(bytes), "r"(mbar) : "memory")

// ---- fast, overflow-safe activations (error ~1e-6) ----
__device__ __forceinline__ float tanh_fast(float x) {
    float ax = fabsf(x);
    float t  = __expf(-2.0f * ax);           // in (0,1], no overflow
    float r  = __fdividef(1.0f - t, 1.0f + t);
    return copysignf(r, x);
}
__device__ __forceinline__ float sig_fast(float x) {
    return 0.5f * tanh_fast(0.5f * x) + 0.5f;
}

// ---------------------------------------------------------------------------
// bf16 GEMM v2 (x-projection): explicit 3-term split over [hi|lo] panels.
// Per 64-k chunk stage A_h/A_l/B_h/B_l once; issue AhBh + AhBl + AlBh.
// CTA 128x64, 8 warps (32x32), 2-stage double buffer, 2 CTAs/SM.
#define G2_AW  (128 * 36)
#define G2_BW  (64 * 36)
#define G2_STW (2 * G2_AW + 2 * G2_BW)       // 13824 words / stage
#define G2_SMEM_BYTES (2 * G2_STW * 4)        // 110592 B

__global__ __launch_bounds__(256, 2) void gemm_x2(
    const __nv_bfloat16* __restrict__ A, int lda,
    const __nv_bfloat16* __restrict__ B, int ldb,
    const float* __restrict__ bias, int D)
{
    extern __shared__ uint32_t smg[];

    const int tid  = threadIdx.x;
    const int n0   = blockIdx.x * 64;
    const int m0   = blockIdx.y * 128;
    const int wid  = tid >> 5, lane = tid & 31;
    const int wm   = (wid >> 1) * 32;
    const int wn   = (wid & 1) * 32;
    const int g    = lane >> 2, t = lane & 3;

    const uint32_t smb = smaddr(smg);
    const int ahoff = (wm + (lane & 15)) * 36 + (lane >> 4) * 4;
    const int bhoff = 2 * G2_AW
                    + (wn + ((lane >> 4) & 1) * 8 + (lane & 7)) * 36
                    + ((lane >> 3) & 1) * 4;

    float acc[2][4][4];
#pragma unroll
    for (int mt = 0; mt < 2; mt++)
#pragma unroll
        for (int nt = 0; nt < 4; nt++)
#pragma unroll
            for (int i = 0; i < 4; i++) acc[mt][nt][i] = 0.0f;

    const int nch = D / 64;

    auto stage = [&](int st, int k0) {
        uint32_t base = smb + st * (G2_STW * 4);
#pragma unroll
        for (int i = 0; i < 4; i++) {          // A_h + A_l: 128 rows x 8 cps
            int q = i * 256 + tid;
            int r = q >> 3, c = q & 7;
            const __nv_bfloat16* ar = A + (size_t)(m0 + r) * lda + k0 + c * 8;
            CP16(base + (r * 36 + c * 4) * 4, ar);
            CP16(base + (G2_AW + r * 36 + c * 4) * 4, ar + D);
        }
#pragma unroll
        for (int i = 0; i < 2; i++) {          // B_h + B_l: 64 rows x 8 cps
            int q = i * 256 + tid;
            int r = q >> 3, c = q & 7;
            const __nv_bfloat16* br = B + (size_t)(n0 + r) * ldb + k0 + c * 8;
            CP16(base + (2 * G2_AW + r * 36 + c * 4) * 4, br);
            CP16(base + (2 * G2_AW + G2_BW + r * 36 + c * 4) * 4, br + D);
        }
        CPCOMMIT();
    };

    stage(0, 0);

    for (int ch = 0; ch < nch; ch++) {
        if (ch + 1 < nch) { stage((ch + 1) & 1, (ch + 1) * 64); cpwaitc<1>(); }
        else              { cpwaitc<0>(); }
        __syncthreads();

        const uint32_t sb = smb + (ch & 1) * (G2_STW * 4);
        const uint32_t sA = sb + ahoff * 4;
        const uint32_t sB = sb + bhoff * 4;

#pragma unroll
        for (int kk = 0; kk < 4; kk++) {
            uint32_t ah0[4], ah1[4], al0[4], al1[4];
            uint32_t bh0[4], bh1[4], bl0[4], bl1[4];
            ldsm4(ah0, sA + kk * 32);
            ldsm4(ah1, sA + 16 * 36 * 4 + kk * 32);
            ldsm4(al0, sA + G2_AW * 4 + kk * 32);
            ldsm4(al1, sA + (G2_AW + 16 * 36) * 4 + kk * 32);
            ldsm4(bh0, sB + kk * 32);
            ldsm4(bh1, sB + 16 * 36 * 4 + kk * 32);
            ldsm4(bl0, sB + G2_BW * 4 + kk * 32);
            ldsm4(bl1, sB + (G2_BW + 16 * 36) * 4 + kk * 32);

            // Ah x Bh
            mma16816(acc[0][0], ah0, bh0);      mma16816(acc[1][0], ah1, bh0);
            mma16816(acc[0][1], ah0, bh0 + 2);  mma16816(acc[1][1], ah1, bh0 + 2);
            mma16816(acc[0][2], ah0, bh1);      mma16816(acc[1][2], ah1, bh1);
            mma16816(acc[0][3], ah0, bh1 + 2);  mma16816(acc[1][3], ah1, bh1 + 2);
            // Ah x Bl
            mma16816(acc[0][0], ah0, bl0);      mma16816(acc[1][0], ah1, bl0);
            mma16816(acc[0][1], ah0, bl0 + 2);  mma16816(acc[1][1], ah1, bl0 + 2);
            mma16816(acc[0][2], ah0, bl1);      mma16816(acc[1][2], ah1, bl1);
            mma16816(acc[0][3], ah0, bl1 + 2);  mma16816(acc[1][3], ah1, bl1 + 2);
            // Al x Bh
            mma16816(acc[0][0], al0, bh0);      mma16816(acc[1][0], al1, bh0);
            mma16816(acc[0][1], al0, bh0 + 2);  mma16816(acc[1][1], al1, bh0 + 2);
            mma16816(acc[0][2], al0, bh1);      mma16816(acc[1][2], al1, bh1);
            mma16816(acc[0][3], al0, bh1 + 2);  mma16816(acc[1][3], al1, bh1 + 2);
        }
        __syncthreads();   // protect buffer (ch&1) before restage at ch+2
    }

    // epilogue: scatter to g_gxT[s][n][b] + bias
#pragma unroll
    for (int mt = 0; mt < 2; mt++) {
        int m1 = m0 + wm + mt * 16 + g;
        int m2 = m1 + 8;
        int b1 = m1 >> 9, s1 = m1 & 511;
        int b2 = m2 >> 9, s2 = m2 & 511;
#pragma unroll
        for (int nt = 0; nt < 4; nt++) {
            int n = n0 + wn + nt * 8 + 2 * t;
            float2 bv = *(const float2*)&bias[n];
            size_t o1 = ((size_t)s1 * NG + n) * BB + b1;
            size_t o2 = ((size_t)s2 * NG + n) * BB + b2;
            g_gxT[o1]      = acc[mt][nt][0] + bv.x;
            g_gxT[o1 + BB] = acc[mt][nt][1] + bv.y;
            g_gxT[o2]      = acc[mt][nt][2] + bv.x;
            g_gxT[o2 + BB] = acc[mt][nt][3] + bv.y;
        }
    }
}

// ---------------------------------------------------------------------------
// Persistent recurrent kernel v5: two half bulk copies overlap mma phases
// (proven R15); h rows stride 2048 [hi|lo]; fast activations.
#define LHOFFW  16512
#define LROWW   1028
#define LPARTW  49408
#define LMBARW  57856
#define LS_SMEM_BYTES 231488

__global__ __launch_bounds__(256, 1) void lstm_layer(
    const float* __restrict__ W, int ldw, int Din,
    float* __restrict__ out, int layer, int rbase)
{
    extern __shared__ uint32_t smu[];
    uint32_t* Wsh  = smu;
    uint32_t* WslT = smu + LHOFFW;
    float*    part = (float*)(smu + LPARTW);
    const uint32_t smb   = smaddr(smu);
    const uint32_t mbar0 = smb + LMBARW * 4;
    const uint32_t mbar1 = mbar0 + 8;

    const int tid  = threadIdx.x;
    const int j0   = blockIdx.x * 8;
    const int wid  = tid >> 5, lane = tid & 31;
    const int g    = lane >> 2, t4 = lane & 3;

    for (int i = 0; i < 64; i++) {
        int q  = i * 256 + tid;
        int l  = q >> 9;
        int wk = q & 511;
        int gate = l >> 3, jj = l & 7;
        int n = gate * 1024 + j0 + jj;
        float2 v = *(const float2*)(W + (size_t)n * ldw + Din + wk * 2);
        __nv_bfloat16 hx = __float2bfloat16(v.x);
        __nv_bfloat16 hy = __float2bfloat16(v.y);
        __nv_bfloat16 lx = __float2bfloat16(v.x - __bfloat162float(hx));
        __nv_bfloat16 ly = __float2bfloat16(v.y - __bfloat162float(hy));
        Wsh[l * 516 + wk]  = (uint32_t)__bfloat16_as_ushort(hx)
                           | ((uint32_t)__bfloat16_as_ushort(hy) << 16);
        WslT[l * 516 + wk] = (uint32_t)__bfloat16_as_ushort(lx)
                           | ((uint32_t)__bfloat16_as_ushort(ly) << 16);
    }
    if (tid == 0) {
        asm volatile("mbarrier.init.shared.b64 [%0], %1;"
                     :: "r"(mbar0), "r"(1u) : "memory");
        asm volatile("mbarrier.init.shared.b64 [%0], %1;"
                     :: "r"(mbar1), "r"(1u) : "memory");
    }
    __syncthreads();

    uint32_t wl[8][4][2];
#pragma unroll
    for (int sc = 0; sc < 8; sc++) {
        int bw = (sc * 8 + wid) * 8 + t4;
#pragma unroll
        for (int nt = 0; nt < 4; nt++) {
            int rn = nt * 8 + g;
            wl[sc][nt][0] = WslT[rn * 516 + bw];
            wl[sc][nt][1] = WslT[rn * 516 + bw + 4];
        }
    }
    __syncthreads();

    const int uj = tid & 7;
    const int ub = tid >> 3;
    const int ujglob = j0 + uj;

    float c_state = 0.0f;
    float h_last  = 0.0f;

    for (int tstep = 0; tstep < SS; tstep++) {
        size_t gbase = ((size_t)tstep * NG + ujglob) * BB + ub;
        float pi = g_gxT[gbase];
        float pf = g_gxT[gbase + (size_t)1024 * BB];
        float pg = g_gxT[gbase + (size_t)2048 * BB];
        float po = g_gxT[gbase + (size_t)3072 * BB];

        unsigned round = (unsigned)(rbase + tstep + 1);
        __threadfence();
        __syncthreads();
        if (tid == 0) {
            unsigned arrived = atomicAdd(&g_barCnt, 1u) + 1u;
            if (arrived == round * NCTA) {
                atomicExch(&g_barRel, round);
            } else {
                volatile unsigned* rel = &g_barRel;
                while (*rel < round) {}
            }
            __threadfence();
        }
        __syncthreads();

        if (tstep > 0) {
            if (wid == 0) {
                if (lane == 0) {
                    asm volatile(
                        "mbarrier.arrive.expect_tx.shared.b64 _, [%0], %1;"
                        :: "r"(mbar0), "r"(65536u) : "memory");
                } else if (lane == 1) {
                    asm volatile(
                        "mbarrier.arrive.expect_tx.shared.b64 _, [%0], %1;"
                        :: "r"(mbar1), "r"(65536u) : "memory");
                }
                __syncwarp();
                uint32_t dstb = smb + (LHOFFW + lane * LROWW) * 4;
                const __nv_bfloat16* srcp =
                    g_Abig + (size_t)(lane * 512 + tstep - 1) * 2048;
                BULKCP(dstb, srcp, 4096u, (lane < 16) ? mbar0 : mbar1);
            }

            float acc[2][4][4];
#pragma unroll
            for (int mt = 0; mt < 2; mt++)
#pragma unroll
                for (int nt = 0; nt < 4; nt++)
#pragma unroll
                    for (int i = 0; i < 4; i++) acc[mt][nt][i] = 0.0f;

            unsigned par = (unsigned)((tstep - 1) & 1);

            mbar_wait(mbar0, par);
#pragma unroll
            for (int sc = 0; sc < 8; sc++) {
                const int kw = (sc * 8 + wid) * 8 + t4;
                uint32_t ah[4], al[4];
                {
                    int rb = LHOFFW + g * LROWW + kw;
                    ah[0] = smu[rb];
                    ah[1] = smu[rb + 8 * LROWW];
                    ah[2] = smu[rb + 4];
                    ah[3] = smu[rb + 8 * LROWW + 4];
                    al[0] = smu[rb + 512];
                    al[1] = smu[rb + 8 * LROWW + 512];
                    al[2] = smu[rb + 516];
                    al[3] = smu[rb + 8 * LROWW + 516];
                }
#pragma unroll
                for (int nt = 0; nt < 4; nt++) {
                    int rn = nt * 8 + g;
                    uint32_t bh[2];
                    bh[0] = Wsh[rn * 516 + kw];
                    bh[1] = Wsh[rn * 516 + kw + 4];
                    mma16816(acc[0][nt], ah, bh);
                    mma16816(acc[0][nt], ah, wl[sc][nt]);
                    mma16816(acc[0][nt], al, bh);
                }
            }

            mbar_wait(mbar1, par);
#pragma unroll
            for (int sc = 0; sc < 8; sc++) {
                const int kw = (sc * 8 + wid) * 8 + t4;
                uint32_t ah[4], al[4];
                {
                    int rb = LHOFFW + (16 + g) * LROWW + kw;
                    ah[0] = smu[rb];
                    ah[1] = smu[rb + 8 * LROWW];
                    ah[2] = smu[rb + 4];
                    ah[3] = smu[rb + 8 * LROWW + 4];
                    al[0] = smu[rb + 512];
                    al[1] = smu[rb + 8 * LROWW + 512];
                    al[2] = smu[rb + 516];
                    al[3] = smu[rb + 8 * LROWW + 516];
                }
#pragma unroll
                for (int nt = 0; nt < 4; nt++) {
                    int rn = nt * 8 + g;
                    uint32_t bh[2];
                    bh[0] = Wsh[rn * 516 + kw];
                    bh[1] = Wsh[rn * 516 + kw + 4];
                    mma16816(acc[1][nt], ah, bh);
                    mma16816(acc[1][nt], ah, wl[sc][nt]);
                    mma16816(acc[1][nt], al, bh);
                }
            }

#pragma unroll
            for (int mt = 0; mt < 2; mt++) {
                int b = mt * 16 + g;
#pragma unroll
                for (int nt = 0; nt < 4; nt++) {
                    int l = nt * 8 + 2 * t4;
                    part[(wid * 32 + b) * 33 + l]     = acc[mt][nt][0];
                    part[(wid * 32 + b) * 33 + l + 1] = acc[mt][nt][1];
                    part[(wid * 32 + b + 8) * 33 + l]     = acc[mt][nt][2];
                    part[(wid * 32 + b + 8) * 33 + l + 1] = acc[mt][nt][3];
                }
            }
            __syncthreads();

#pragma unroll
            for (int w = 0; w < 8; w++) {
                int base = (w * 32 + ub) * 33 + uj;
                pi += part[base];
                pf += part[base + 8];
                pg += part[base + 16];
                po += part[base + 24];
            }
        }

        float gi = sig_fast(pi);
        float gf = sig_fast(pf);
        float gg = tanh_fast(pg);
        float go = sig_fast(po);
        c_state = gf * c_state + gi * gg;
        float h = go * tanh_fast(c_state);
        h_last = h;
        __nv_bfloat16 hh = __float2bfloat16(h);
        __nv_bfloat16 hl = __float2bfloat16(h - __bfloat162float(hh));
        size_t row = (size_t)(ub * 512 + tstep) * 2048;
        g_Abig[row + ujglob]        = hh;
        g_Abig[row + 1024 + ujglob] = hl;
    }

    out[32768 + layer * 32768 + ub * 1024 + ujglob] = h_last;
    out[98304 + layer * 32768 + ub * 1024 + ujglob] = c_state;
    if (layer == 1) out[ub * 1024 + ujglob] = h_last;
}

// ---------------------------------------------------------------------------
extern "C" void kernel_launch(void* const* d_in, const int* in_sizes, int n_in,
                              void* d_out, int out_size)
{
    const float* x  = (const float*)d_in[0];
    const float* W0 = (const float*)d_in[1];
    const float* b0 = (const float*)d_in[2];
    const float* W1 = (const float*)d_in[3];
    const float* b1 = (const float*)d_in[4];
    float* out = (float*)d_out;

    cudaFuncSetAttribute(lstm_layer,
        cudaFuncAttributeMaxDynamicSharedMemorySize, LS_SMEM_BYTES);
    cudaFuncSetAttribute(gemm_x2,
        cudaFuncAttributeMaxDynamicSharedMemorySize, G2_SMEM_BYTES);

    __nv_bfloat16 *Abig, *B0big, *B1big;
    cudaGetSymbolAddress((void**)&Abig,  g_Abig);
    cudaGetSymbolAddress((void**)&B0big, g_B0big);
    cudaGetSymbolAddress((void**)&B1big, g_B1big);

    split_x<<<(16384 * 512 + 255) / 256, 256>>>(x);                       // 0
    split_w<<<(4096 * 512 + 255) / 256, 256>>>(W0, INF + HH, 512, B0big, 1024); // 1
    gemm_x2<<<dim3(64, 128), 256, G2_SMEM_BYTES>>>(
        Abig, 2048, B0big, 1024, b0, 512);                                // 2
    lstm_layer<<<NCTA, 256, LS_SMEM_BYTES>>>(W0, INF + HH, INF, out, 0, 0); // 3
    split_w<<<(4096 * 1024 + 255) / 256, 256>>>(W1, HH + HH, 1024, B1big, 2048); // 4
    gemm_x2<<<dim3(64, 128), 256, G2_SMEM_BYTES>>>(
        Abig, 2048, B1big, 2048, b1, 1024);                               // 5
    lstm_layer<<<NCTA, 256, LS_SMEM_BYTES>>>(W1, HH + HH, HH, out, 1, 512); // 6
}